// round 1
// baseline (speedup 1.0000x reference)
#include <cuda_runtime.h>

#define N_NODES 50000
#define E_EDGES 800000
#define D 128
#define NGRAPH 64

// ---------------- scratch (static __device__, no allocation) ----------------
__device__ float g_h1[N_NODES * D];     // h = x@W buffers (reused for layer2)
__device__ float g_h2[N_NODES * D];
__device__ float g_x11[N_NODES * D];
__device__ float g_x12[N_NODES * D];
__device__ float g_x21[N_NODES * D];
__device__ float g_x22[N_NODES * D];
__device__ float g_deg1[N_NODES];
__device__ float g_deg2[N_NODES];
__device__ float g_dis1[N_NODES];
__device__ float g_dis2[N_NODES];
__device__ float g_sums[NGRAPH * D];
__device__ float g_cnt[NGRAPH];

// ---------------- helpers ----------------
__device__ __forceinline__ void red_add_v4(float* p, float a, float b, float c, float d) {
    asm volatile(
        "{\n\t"
        ".reg .u64 q;\n\t"
        "cvta.to.global.u64 q, %0;\n\t"
        "red.global.add.v4.f32 [q], {%1, %2, %3, %4};\n\t"
        "}"
        :: "l"(p), "f"(a), "f"(b), "f"(c), "f"(d) : "memory");
}

// ---------------- kernels ----------------

// init: self-loop degree = 1, zero pooling accumulators
__global__ void k_init() {
    int i = blockIdx.x * blockDim.x + threadIdx.x;
    if (i < N_NODES) { g_deg1[i] = 1.0f; g_deg2[i] = 1.0f; }
    if (i < NGRAPH * D) g_sums[i] = 0.0f;
    if (i < NGRAPH) g_cnt[i] = 0.0f;
}

// accumulate edge weights into degree (both graphs in one launch)
__global__ void k_deg(const int* __restrict__ ei1, const float* __restrict__ ew1,
                      const int* __restrict__ ei2, const float* __restrict__ ew2) {
    int t = blockIdx.x * blockDim.x + threadIdx.x;
    if (t < E_EDGES) {
        atomicAdd(&g_deg1[ei1[E_EDGES + t]], ew1[t]);
    } else if (t < 2 * E_EDGES) {
        int e = t - E_EDGES;
        atomicAdd(&g_deg2[ei2[E_EDGES + e]], ew2[e]);
    }
}

__global__ void k_dis() {
    int i = blockIdx.x * blockDim.x + threadIdx.x;
    if (i < N_NODES) {
        g_dis1[i] = rsqrtf(g_deg1[i]);
        g_dis2[i] = rsqrtf(g_deg2[i]);
    }
}

// C[N,128] = A[N,128] @ W[128,128]; blockIdx.y selects (A0,C0)/(A1,C1)
__global__ __launch_bounds__(256) void k_gemm(
    const float* __restrict__ A0, const float* __restrict__ A1,
    const float* __restrict__ W, float* __restrict__ C0, float* __restrict__ C1) {
    const float* A = blockIdx.y ? A1 : A0;
    float* C = blockIdx.y ? C1 : C0;

    __shared__ __align__(16) float As[16][132];   // transposed: As[k][row]
    __shared__ __align__(16) float Ws[16][128];   // Ws[k][col]

    int row0 = blockIdx.x * 128;
    int t = threadIdx.x;
    int tx = t & 15;   // col group
    int ty = t >> 4;   // row group

    float acc[8][8];
#pragma unroll
    for (int i = 0; i < 8; i++)
#pragma unroll
        for (int j = 0; j < 8; j++) acc[i][j] = 0.0f;

    for (int kk = 0; kk < 128; kk += 16) {
        // load A tile 128x16 (transposed into As)
#pragma unroll
        for (int i = 0; i < 2; i++) {
            int f4 = t * 2 + i;        // 0..511
            int r = f4 >> 2;           // 0..127
            int q = f4 & 3;            // 0..3
            int grow = row0 + r;
            float4 v = make_float4(0.f, 0.f, 0.f, 0.f);
            if (grow < N_NODES)
                v = *(const float4*)(A + grow * 128 + kk + q * 4);
            As[q * 4 + 0][r] = v.x;
            As[q * 4 + 1][r] = v.y;
            As[q * 4 + 2][r] = v.z;
            As[q * 4 + 3][r] = v.w;
        }
        // load W tile 16x128
#pragma unroll
        for (int i = 0; i < 2; i++) {
            int f4 = t * 2 + i;
            int r = f4 >> 5;           // 0..15
            int c = (f4 & 31) * 4;     // 0..124
            *(float4*)&Ws[r][c] = *(const float4*)(W + (kk + r) * 128 + c);
        }
        __syncthreads();

#pragma unroll
        for (int k = 0; k < 16; k++) {
            float a[8], b[8];
            *(float4*)(a)     = *(const float4*)&As[k][ty * 8];
            *(float4*)(a + 4) = *(const float4*)&As[k][ty * 8 + 4];
            *(float4*)(b)     = *(const float4*)&Ws[k][tx * 8];
            *(float4*)(b + 4) = *(const float4*)&Ws[k][tx * 8 + 4];
#pragma unroll
            for (int i = 0; i < 8; i++)
#pragma unroll
                for (int j = 0; j < 8; j++) acc[i][j] += a[i] * b[j];
        }
        __syncthreads();
    }

#pragma unroll
    for (int i = 0; i < 8; i++) {
        int r = row0 + ty * 8 + i;
        if (r < N_NODES) {
            float4 v0 = make_float4(acc[i][0], acc[i][1], acc[i][2], acc[i][3]);
            float4 v1 = make_float4(acc[i][4], acc[i][5], acc[i][6], acc[i][7]);
            *(float4*)(C + r * 128 + tx * 8)     = v0;
            *(float4*)(C + r * 128 + tx * 8 + 4) = v1;
        }
    }
}

// X = dis^2 * H + bias (self-loop contribution + bias), for both graphs
__global__ __launch_bounds__(256) void k_selfinit(
    const float* __restrict__ Ha, const float* __restrict__ Hb,
    float* __restrict__ Xa, float* __restrict__ Xb,
    const float* __restrict__ bias) {
    int t = blockIdx.x * blockDim.x + threadIdx.x;   // float4 index
    if (t >= N_NODES * 32) return;
    int i = t >> 5;
    int c4 = (t & 31) * 4;
    float4 bv = *(const float4*)(bias + c4);
    float n1 = g_dis1[i]; n1 *= n1;
    float n2 = g_dis2[i]; n2 *= n2;
    float4 ha = *(const float4*)(Ha + i * 128 + c4);
    float4 hb = *(const float4*)(Hb + i * 128 + c4);
    float4 xa = make_float4(n1 * ha.x + bv.x, n1 * ha.y + bv.y, n1 * ha.z + bv.z, n1 * ha.w + bv.w);
    float4 xb = make_float4(n2 * hb.x + bv.x, n2 * hb.y + bv.y, n2 * hb.z + bv.z, n2 * hb.w + bv.w);
    *(float4*)(Xa + i * 128 + c4) = xa;
    *(float4*)(Xb + i * 128 + c4) = xb;
}

// edge scatter: one warp per edge, both graphs in one launch
__global__ __launch_bounds__(256) void k_scatter(
    const int* __restrict__ ei1, const float* __restrict__ ew1,
    const int* __restrict__ ei2, const float* __restrict__ ew2,
    const float* __restrict__ H1, const float* __restrict__ H2,
    float* __restrict__ X1, float* __restrict__ X2) {
    int wid = (blockIdx.x * blockDim.x + threadIdx.x) >> 5;
    int lane = threadIdx.x & 31;
    if (wid >= 2 * E_EDGES) return;
    const int* ei; const float* ew; const float* H; float* X; const float* dis;
    int e;
    if (wid < E_EDGES) { e = wid;            ei = ei1; ew = ew1; H = H1; X = X1; dis = g_dis1; }
    else               { e = wid - E_EDGES;  ei = ei2; ew = ew2; H = H2; X = X2; dis = g_dis2; }
    int s = ei[e];
    int d = ei[E_EDGES + e];
    float norm = dis[s] * ew[e] * dis[d];
    float4 v = *(const float4*)(H + s * 128 + lane * 4);
    red_add_v4(X + d * 128 + lane * 4, norm * v.x, norm * v.y, norm * v.z, norm * v.w);
}

// pool: one warp per node, x = (x12-x11)*(x22-x21), reduce into per-graph sums
__global__ __launch_bounds__(256) void k_pool(const int* __restrict__ batch) {
    int wid = (blockIdx.x * blockDim.x + threadIdx.x) >> 5;
    int lane = threadIdx.x & 31;
    if (wid >= N_NODES) return;
    int g = batch[wid];
    int off = wid * 128 + lane * 4;
    float4 a11 = *(const float4*)(g_x11 + off);
    float4 a12 = *(const float4*)(g_x12 + off);
    float4 a21 = *(const float4*)(g_x21 + off);
    float4 a22 = *(const float4*)(g_x22 + off);
    float px = (a12.x - a11.x) * (a22.x - a21.x);
    float py = (a12.y - a11.y) * (a22.y - a21.y);
    float pz = (a12.z - a11.z) * (a22.z - a21.z);
    float pw = (a12.w - a11.w) * (a22.w - a21.w);
    red_add_v4(g_sums + g * 128 + lane * 4, px, py, pz, pw);
    if (lane == 0) atomicAdd(&g_cnt[g], 1.0f);
}

// final MLP: one block per graph, 128 threads
__global__ __launch_bounds__(128) void k_mlp(
    const float* __restrict__ M1w, const float* __restrict__ M1b,
    const float* __restrict__ M2w, const float* __restrict__ M2b,
    const float* __restrict__ M3w, const float* __restrict__ M3b,
    const float* __restrict__ M4w, const float* __restrict__ M4b,
    float* __restrict__ out) {
    __shared__ float gv[128], h1s[128], h2s[64], h3s[32];
    int g = blockIdx.x;
    int t = threadIdx.x;
    float cnt = fmaxf(g_cnt[g], 1.0f);
    gv[t] = g_sums[g * 128 + t] / cnt;
    __syncthreads();
    float acc = M1b[t];
#pragma unroll 8
    for (int c = 0; c < 128; c++) acc += gv[c] * M1w[c * 128 + t];
    h1s[t] = acc;
    __syncthreads();
    if (t < 64) {
        acc = M2b[t];
#pragma unroll 8
        for (int c = 0; c < 128; c++) acc += h1s[c] * M2w[c * 64 + t];
        h2s[t] = acc;
    }
    __syncthreads();
    if (t < 32) {
        acc = M3b[t];
#pragma unroll 8
        for (int c = 0; c < 64; c++) acc += h2s[c] * M3w[c * 32 + t];
        h3s[t] = acc;
    }
    __syncthreads();
    if (t < 32) {
        float v = h3s[t] * M4w[t];
#pragma unroll
        for (int off = 16; off > 0; off >>= 1)
            v += __shfl_down_sync(0xffffffff, v, off);
        if (t == 0) out[g] = v + M4b[0];
    }
}

// ---------------- launch ----------------
extern "C" void kernel_launch(void* const* d_in, const int* in_sizes, int n_in,
                              void* d_out, int out_size) {
    const int*   ei1  = (const int*)d_in[0];
    const float* ew1  = (const float*)d_in[1];
    const int*   ei2  = (const int*)d_in[2];
    const float* ew2  = (const float*)d_in[3];
    const float* fm0  = (const float*)d_in[4];
    const float* fm1  = (const float*)d_in[5];
    const int*   batch = (const int*)d_in[6];
    const float* W1  = (const float*)d_in[7];
    const float* b1  = (const float*)d_in[8];
    const float* W2  = (const float*)d_in[9];
    const float* b2  = (const float*)d_in[10];
    const float* M1w = (const float*)d_in[11];
    const float* M1b = (const float*)d_in[12];
    const float* M2w = (const float*)d_in[13];
    const float* M2b = (const float*)d_in[14];
    const float* M3w = (const float*)d_in[15];
    const float* M3b = (const float*)d_in[16];
    const float* M4w = (const float*)d_in[17];
    const float* M4b = (const float*)d_in[18];
    float* out = (float*)d_out;

    void *p_h1, *p_h2, *p_x11, *p_x12, *p_x21, *p_x22;
    cudaGetSymbolAddress(&p_h1, g_h1);
    cudaGetSymbolAddress(&p_h2, g_h2);
    cudaGetSymbolAddress(&p_x11, g_x11);
    cudaGetSymbolAddress(&p_x12, g_x12);
    cudaGetSymbolAddress(&p_x21, g_x21);
    cudaGetSymbolAddress(&p_x22, g_x22);
    float* h1 = (float*)p_h1;   float* h2 = (float*)p_h2;
    float* x11 = (float*)p_x11; float* x12 = (float*)p_x12;
    float* x21 = (float*)p_x21; float* x22 = (float*)p_x22;

    const int TPB = 256;
    int nodeBlocks = (N_NODES + TPB - 1) / TPB;
    int edgeBlocks = (2 * E_EDGES + TPB - 1) / TPB;
    int f4Blocks   = (N_NODES * 32 + TPB - 1) / TPB;      // per-channel float4 threads
    int warpEdgeBlocks = (2 * E_EDGES * 32) / TPB;        // warp per edge
    int warpNodeBlocks = (N_NODES * 32 + TPB - 1) / TPB;  // warp per node

    k_init<<<nodeBlocks, TPB>>>();
    k_deg<<<edgeBlocks, TPB>>>(ei1, ew1, ei2, ew2);
    k_dis<<<nodeBlocks, TPB>>>();

    dim3 gg((N_NODES + 127) / 128, 2);
    // layer 1
    k_gemm<<<gg, TPB>>>(fm0, fm1, W1, h1, h2);
    k_selfinit<<<f4Blocks, TPB>>>(h1, h2, x11, x12, b1);
    k_scatter<<<warpEdgeBlocks, TPB>>>(ei1, ew1, ei2, ew2, h1, h2, x11, x12);
    // layer 2
    k_gemm<<<gg, TPB>>>(x11, x12, W2, h1, h2);
    k_selfinit<<<f4Blocks, TPB>>>(h1, h2, x21, x22, b2);
    k_scatter<<<warpEdgeBlocks, TPB>>>(ei1, ew1, ei2, ew2, h1, h2, x21, x22);
    // pool + MLP
    k_pool<<<warpNodeBlocks, TPB>>>(batch);
    k_mlp<<<NGRAPH, 128>>>(M1w, M1b, M2w, M2b, M3w, M3b, M4w, M4b, out);
}

// round 2
// speedup vs baseline: 1.3671x; 1.3671x over previous
#include <cuda_runtime.h>

#define N_NODES 50000
#define E_EDGES 800000
#define D 128
#define NGRAPH 64

// ---------------- scratch (static __device__, no allocation) ----------------
__device__ float g_h1[N_NODES * D];
__device__ float g_h2[N_NODES * D];
__device__ float g_x11[N_NODES * D];
__device__ float g_x12[N_NODES * D];
__device__ float g_deg1[N_NODES];
__device__ float g_deg2[N_NODES];
__device__ float g_dis1[N_NODES];
__device__ float g_dis2[N_NODES];
__device__ int   g_c1[N_NODES];       // in-degree counts
__device__ int   g_c2[N_NODES];
__device__ int   g_rp1[N_NODES + 1];  // CSR row pointers (by destination)
__device__ int   g_rp2[N_NODES + 1];
__device__ int   g_cur1[N_NODES];     // fill cursors
__device__ int   g_cur2[N_NODES];
__device__ int2  g_m1[E_EDGES];       // (src, float_bits(norm))
__device__ int2  g_m2[E_EDGES];
__device__ float g_sums[NGRAPH * D];
__device__ float g_cnt[NGRAPH];

// ---------------- helpers ----------------
__device__ __forceinline__ void red_add_v4(float* p, float a, float b, float c, float d) {
    asm volatile(
        "{\n\t"
        ".reg .u64 q;\n\t"
        "cvta.to.global.u64 q, %0;\n\t"
        "red.global.add.v4.f32 [q], {%1, %2, %3, %4};\n\t"
        "}"
        :: "l"(p), "f"(a), "f"(b), "f"(c), "f"(d) : "memory");
}

__device__ __forceinline__ unsigned long long dup2(float x) {
    unsigned long long r;
    asm("mov.b64 %0, {%1, %1};" : "=l"(r) : "f"(x));
    return r;
}
__device__ __forceinline__ void fma2(unsigned long long& c, unsigned long long a,
                                     unsigned long long b) {
    asm("fma.rn.f32x2 %0, %1, %2, %0;" : "+l"(c) : "l"(a), "l"(b));
}

// ---------------- kernels ----------------

__global__ void k_init() {
    int i = blockIdx.x * blockDim.x + threadIdx.x;
    if (i < N_NODES) {
        g_deg1[i] = 1.0f; g_deg2[i] = 1.0f;
        g_c1[i] = 0; g_c2[i] = 0;
    }
    if (i < NGRAPH * D) g_sums[i] = 0.0f;
    if (i < NGRAPH) g_cnt[i] = 0.0f;
}

// degree (weights) + in-degree histogram, both graphs
__global__ void k_deg(const int* __restrict__ ei1, const float* __restrict__ ew1,
                      const int* __restrict__ ei2, const float* __restrict__ ew2) {
    int t = blockIdx.x * blockDim.x + threadIdx.x;
    if (t < E_EDGES) {
        int d = ei1[E_EDGES + t];
        atomicAdd(&g_deg1[d], ew1[t]);
        atomicAdd(&g_c1[d], 1);
    } else if (t < 2 * E_EDGES) {
        int e = t - E_EDGES;
        int d = ei2[E_EDGES + e];
        atomicAdd(&g_deg2[d], ew2[e]);
        atomicAdd(&g_c2[d], 1);
    }
}

// exclusive scan of counts -> row pointers + cursors. One block per graph.
__global__ __launch_bounds__(1024) void k_scan() {
    const int T = 1024;
    const int CH = (N_NODES + T - 1) / T;  // 49
    int g = blockIdx.x;
    const int* cnt = g ? g_c2 : g_c1;
    int* rp = g ? g_rp2 : g_rp1;
    int* cur = g ? g_cur2 : g_cur1;
    __shared__ int sh[T];
    int t = threadIdx.x;
    int base = t * CH;
    int s = 0;
    for (int i = 0; i < CH; i++) {
        int idx = base + i;
        s += (idx < N_NODES) ? cnt[idx] : 0;
    }
    sh[t] = s;
    __syncthreads();
    for (int off = 1; off < T; off <<= 1) {
        int v = (t >= off) ? sh[t - off] : 0;
        __syncthreads();
        sh[t] += v;
        __syncthreads();
    }
    int run = (t == 0) ? 0 : sh[t - 1];
    for (int i = 0; i < CH; i++) {
        int idx = base + i;
        if (idx < N_NODES) {
            rp[idx] = run;
            cur[idx] = run;
            run += cnt[idx];
        }
    }
    if (t == T - 1) rp[N_NODES] = run;
}

__global__ void k_dis() {
    int i = blockIdx.x * blockDim.x + threadIdx.x;
    if (i < N_NODES) {
        g_dis1[i] = rsqrtf(g_deg1[i]);
        g_dis2[i] = rsqrtf(g_deg2[i]);
    }
}

// fill CSR with (src, norm)
__global__ void k_fill(const int* __restrict__ ei1, const float* __restrict__ ew1,
                       const int* __restrict__ ei2, const float* __restrict__ ew2) {
    int t = blockIdx.x * blockDim.x + threadIdx.x;
    if (t < E_EDGES) {
        int s = ei1[t], d = ei1[E_EDGES + t];
        float norm = g_dis1[s] * ew1[t] * g_dis1[d];
        int pos = atomicAdd(&g_cur1[d], 1);
        g_m1[pos] = make_int2(s, __float_as_int(norm));
    } else if (t < 2 * E_EDGES) {
        int e = t - E_EDGES;
        int s = ei2[e], d = ei2[E_EDGES + e];
        float norm = g_dis2[s] * ew2[e] * g_dis2[d];
        int pos = atomicAdd(&g_cur2[d], 1);
        g_m2[pos] = make_int2(s, __float_as_int(norm));
    }
}

// C[N,128] = A[N,128] @ W[128,128]; blockIdx.y selects graph. f32x2 inner loop.
__global__ __launch_bounds__(256) void k_gemm(
    const float* __restrict__ A0, const float* __restrict__ A1,
    const float* __restrict__ W, float* __restrict__ C0, float* __restrict__ C1) {
    const float* A = blockIdx.y ? A1 : A0;
    float* C = blockIdx.y ? C1 : C0;

    __shared__ __align__(16) float As[16][132];   // As[k][row] (row-pairs contiguous)
    __shared__ __align__(16) float Ws[16][128];   // Ws[k][col]

    int row0 = blockIdx.x * 128;
    int t = threadIdx.x;
    int tx = t & 15;   // col group (8 cols)
    int ty = t >> 4;   // row group (8 rows)

    // acc2[i2][j]: rows (ty*8+2*i2, +1) packed, col tx*8+j
    unsigned long long acc2[4][8];
#pragma unroll
    for (int i = 0; i < 4; i++)
#pragma unroll
        for (int j = 0; j < 8; j++) acc2[i][j] = 0ull;

    for (int kk = 0; kk < 128; kk += 16) {
#pragma unroll
        for (int i = 0; i < 2; i++) {
            int f4 = t * 2 + i;
            int r = f4 >> 2;
            int q = f4 & 3;
            int grow = row0 + r;
            float4 v = make_float4(0.f, 0.f, 0.f, 0.f);
            if (grow < N_NODES)
                v = *(const float4*)(A + grow * 128 + kk + q * 4);
            As[q * 4 + 0][r] = v.x;
            As[q * 4 + 1][r] = v.y;
            As[q * 4 + 2][r] = v.z;
            As[q * 4 + 3][r] = v.w;
        }
#pragma unroll
        for (int i = 0; i < 2; i++) {
            int f4 = t * 2 + i;
            int r = f4 >> 5;
            int c = (f4 & 31) * 4;
            *(float4*)&Ws[r][c] = *(const float4*)(W + (kk + r) * 128 + c);
        }
        __syncthreads();

#pragma unroll
        for (int k = 0; k < 16; k++) {
            // A pairs come free from contiguous rows
            ulonglong2 av0 = *(const ulonglong2*)&As[k][ty * 8];
            ulonglong2 av1 = *(const ulonglong2*)&As[k][ty * 8 + 4];
            unsigned long long ap[4] = {av0.x, av0.y, av1.x, av1.y};
            float4 b0 = *(const float4*)&Ws[k][tx * 8];
            float4 b1 = *(const float4*)&Ws[k][tx * 8 + 4];
            unsigned long long bd[8];
            bd[0] = dup2(b0.x); bd[1] = dup2(b0.y); bd[2] = dup2(b0.z); bd[3] = dup2(b0.w);
            bd[4] = dup2(b1.x); bd[5] = dup2(b1.y); bd[6] = dup2(b1.z); bd[7] = dup2(b1.w);
#pragma unroll
            for (int i = 0; i < 4; i++)
#pragma unroll
                for (int j = 0; j < 8; j++) fma2(acc2[i][j], ap[i], bd[j]);
        }
        __syncthreads();
    }

#pragma unroll
    for (int i2 = 0; i2 < 4; i2++) {
        float2 f[8];
#pragma unroll
        for (int j = 0; j < 8; j++) f[j] = *(float2*)&acc2[i2][j];
#pragma unroll
        for (int rs = 0; rs < 2; rs++) {
            int r = row0 + ty * 8 + i2 * 2 + rs;
            if (r < N_NODES) {
                float4 v0, v1;
                v0.x = rs ? f[0].y : f[0].x; v0.y = rs ? f[1].y : f[1].x;
                v0.z = rs ? f[2].y : f[2].x; v0.w = rs ? f[3].y : f[3].x;
                v1.x = rs ? f[4].y : f[4].x; v1.y = rs ? f[5].y : f[5].x;
                v1.z = rs ? f[6].y : f[6].x; v1.w = rs ? f[7].y : f[7].x;
                *(float4*)(C + r * 128 + tx * 8) = v0;
                *(float4*)(C + r * 128 + tx * 8 + 4) = v1;
            }
        }
    }
}

// aggregation layer 1: warp per (graph, node). X = sum_in norm*H[s] + dis^2*H[d] + b
__global__ __launch_bounds__(256) void k_agg1(
    const float* __restrict__ H1, const float* __restrict__ H2,
    float* __restrict__ X1, float* __restrict__ X2,
    const float* __restrict__ bias) {
    int wid = (blockIdx.x * blockDim.x + threadIdx.x) >> 5;
    int lane = threadIdx.x & 31;
    if (wid >= 2 * N_NODES) return;
    int g = wid >= N_NODES;
    int d = wid - g * N_NODES;
    const int2* meta = g ? g_m2 : g_m1;
    const int* rp = g ? g_rp2 : g_rp1;
    const float* H = g ? H2 : H1;
    float* X = g ? X2 : X1;
    const float* dis = g ? g_dis2 : g_dis1;

    int beg = rp[d], end = rp[d + 1];
    float n2 = dis[d]; n2 *= n2;
    float4 bv = *(const float4*)(bias + lane * 4);
    float4 hd = *(const float4*)(H + d * 128 + lane * 4);
    float4 acc = make_float4(fmaf(n2, hd.x, bv.x), fmaf(n2, hd.y, bv.y),
                             fmaf(n2, hd.z, bv.z), fmaf(n2, hd.w, bv.w));

    for (int base = beg; base < end; base += 32) {
        int2 mm = make_int2(0, 0);
        if (base + lane < end) mm = __ldg(&meta[base + lane]);
        int m = min(32, end - base);
        int j = 0;
        for (; j + 4 <= m; j += 4) {
            int s0 = __shfl_sync(0xffffffffu, mm.x, j);
            int s1 = __shfl_sync(0xffffffffu, mm.x, j + 1);
            int s2 = __shfl_sync(0xffffffffu, mm.x, j + 2);
            int s3 = __shfl_sync(0xffffffffu, mm.x, j + 3);
            float w0 = __int_as_float(__shfl_sync(0xffffffffu, mm.y, j));
            float w1 = __int_as_float(__shfl_sync(0xffffffffu, mm.y, j + 1));
            float w2 = __int_as_float(__shfl_sync(0xffffffffu, mm.y, j + 2));
            float w3 = __int_as_float(__shfl_sync(0xffffffffu, mm.y, j + 3));
            float4 v0 = __ldg((const float4*)(H + s0 * 128 + lane * 4));
            float4 v1 = __ldg((const float4*)(H + s1 * 128 + lane * 4));
            float4 v2 = __ldg((const float4*)(H + s2 * 128 + lane * 4));
            float4 v3 = __ldg((const float4*)(H + s3 * 128 + lane * 4));
            acc.x += w0 * v0.x + w1 * v1.x + w2 * v2.x + w3 * v3.x;
            acc.y += w0 * v0.y + w1 * v1.y + w2 * v2.y + w3 * v3.y;
            acc.z += w0 * v0.z + w1 * v1.z + w2 * v2.z + w3 * v3.z;
            acc.w += w0 * v0.w + w1 * v1.w + w2 * v2.w + w3 * v3.w;
        }
        for (; j < m; j++) {
            int s = __shfl_sync(0xffffffffu, mm.x, j);
            float w = __int_as_float(__shfl_sync(0xffffffffu, mm.y, j));
            float4 v = __ldg((const float4*)(H + s * 128 + lane * 4));
            acc.x += w * v.x; acc.y += w * v.y; acc.z += w * v.z; acc.w += w * v.w;
        }
    }
    *(float4*)(X + d * 128 + lane * 4) = acc;
}

// aggregation layer 2 fused with pooling: warp per node, both graphs,
// x = (x12-x11)*(x22-x21), red into g_sums[batch[d]]
__global__ __launch_bounds__(256) void k_agg2(
    const float* __restrict__ H1, const float* __restrict__ H2,
    const float* __restrict__ bias, const int* __restrict__ batch) {
    int wid = (blockIdx.x * blockDim.x + threadIdx.x) >> 5;
    int lane = threadIdx.x & 31;
    if (wid >= N_NODES) return;
    int d = wid;
    float4 bv = *(const float4*)(bias + lane * 4);
    float4 acc1, acc2v;

#pragma unroll
    for (int g = 0; g < 2; g++) {
        const int2* meta = g ? g_m2 : g_m1;
        const int* rp = g ? g_rp2 : g_rp1;
        const float* H = g ? H2 : H1;
        const float* dis = g ? g_dis2 : g_dis1;
        int beg = rp[d], end = rp[d + 1];
        float n2 = dis[d]; n2 *= n2;
        float4 hd = *(const float4*)(H + d * 128 + lane * 4);
        float4 acc = make_float4(fmaf(n2, hd.x, bv.x), fmaf(n2, hd.y, bv.y),
                                 fmaf(n2, hd.z, bv.z), fmaf(n2, hd.w, bv.w));
        for (int base = beg; base < end; base += 32) {
            int2 mm = make_int2(0, 0);
            if (base + lane < end) mm = __ldg(&meta[base + lane]);
            int m = min(32, end - base);
            int j = 0;
            for (; j + 4 <= m; j += 4) {
                int s0 = __shfl_sync(0xffffffffu, mm.x, j);
                int s1 = __shfl_sync(0xffffffffu, mm.x, j + 1);
                int s2 = __shfl_sync(0xffffffffu, mm.x, j + 2);
                int s3 = __shfl_sync(0xffffffffu, mm.x, j + 3);
                float w0 = __int_as_float(__shfl_sync(0xffffffffu, mm.y, j));
                float w1 = __int_as_float(__shfl_sync(0xffffffffu, mm.y, j + 1));
                float w2 = __int_as_float(__shfl_sync(0xffffffffu, mm.y, j + 2));
                float w3 = __int_as_float(__shfl_sync(0xffffffffu, mm.y, j + 3));
                float4 v0 = __ldg((const float4*)(H + s0 * 128 + lane * 4));
                float4 v1 = __ldg((const float4*)(H + s1 * 128 + lane * 4));
                float4 v2 = __ldg((const float4*)(H + s2 * 128 + lane * 4));
                float4 v3 = __ldg((const float4*)(H + s3 * 128 + lane * 4));
                acc.x += w0 * v0.x + w1 * v1.x + w2 * v2.x + w3 * v3.x;
                acc.y += w0 * v0.y + w1 * v1.y + w2 * v2.y + w3 * v3.y;
                acc.z += w0 * v0.z + w1 * v1.z + w2 * v2.z + w3 * v3.z;
                acc.w += w0 * v0.w + w1 * v1.w + w2 * v2.w + w3 * v3.w;
            }
            for (; j < m; j++) {
                int s = __shfl_sync(0xffffffffu, mm.x, j);
                float w = __int_as_float(__shfl_sync(0xffffffffu, mm.y, j));
                float4 v = __ldg((const float4*)(H + s * 128 + lane * 4));
                acc.x += w * v.x; acc.y += w * v.y; acc.z += w * v.z; acc.w += w * v.w;
            }
        }
        if (g == 0) acc1 = acc; else acc2v = acc;
    }

    // pooled product
    int off = d * 128 + lane * 4;
    float4 a11 = *(const float4*)(g_x11 + off);
    float4 a12 = *(const float4*)(g_x12 + off);
    float px = (a12.x - a11.x) * (acc2v.x - acc1.x);
    float py = (a12.y - a11.y) * (acc2v.y - acc1.y);
    float pz = (a12.z - a11.z) * (acc2v.z - acc1.z);
    float pw = (a12.w - a11.w) * (acc2v.w - acc1.w);
    int gph = batch[d];
    red_add_v4(g_sums + gph * 128 + lane * 4, px, py, pz, pw);
    if (lane == 0) atomicAdd(&g_cnt[gph], 1.0f);
}

// final MLP: one block per graph
__global__ __launch_bounds__(128) void k_mlp(
    const float* __restrict__ M1w, const float* __restrict__ M1b,
    const float* __restrict__ M2w, const float* __restrict__ M2b,
    const float* __restrict__ M3w, const float* __restrict__ M3b,
    const float* __restrict__ M4w, const float* __restrict__ M4b,
    float* __restrict__ out) {
    __shared__ float gv[128], h1s[128], h2s[64], h3s[32];
    int g = blockIdx.x;
    int t = threadIdx.x;
    float cnt = fmaxf(g_cnt[g], 1.0f);
    gv[t] = g_sums[g * 128 + t] / cnt;
    __syncthreads();
    float acc = M1b[t];
#pragma unroll 8
    for (int c = 0; c < 128; c++) acc += gv[c] * M1w[c * 128 + t];
    h1s[t] = acc;
    __syncthreads();
    if (t < 64) {
        acc = M2b[t];
#pragma unroll 8
        for (int c = 0; c < 128; c++) acc += h1s[c] * M2w[c * 64 + t];
        h2s[t] = acc;
    }
    __syncthreads();
    if (t < 32) {
        acc = M3b[t];
#pragma unroll 8
        for (int c = 0; c < 64; c++) acc += h2s[c] * M3w[c * 32 + t];
        h3s[t] = acc;
    }
    __syncthreads();
    if (t < 32) {
        float v = h3s[t] * M4w[t];
#pragma unroll
        for (int off = 16; off > 0; off >>= 1)
            v += __shfl_down_sync(0xffffffff, v, off);
        if (t == 0) out[g] = v + M4b[0];
    }
}

// ---------------- launch ----------------
extern "C" void kernel_launch(void* const* d_in, const int* in_sizes, int n_in,
                              void* d_out, int out_size) {
    const int*   ei1  = (const int*)d_in[0];
    const float* ew1  = (const float*)d_in[1];
    const int*   ei2  = (const int*)d_in[2];
    const float* ew2  = (const float*)d_in[3];
    const float* fm0  = (const float*)d_in[4];
    const float* fm1  = (const float*)d_in[5];
    const int*   batch = (const int*)d_in[6];
    const float* W1  = (const float*)d_in[7];
    const float* b1  = (const float*)d_in[8];
    const float* W2  = (const float*)d_in[9];
    const float* b2  = (const float*)d_in[10];
    const float* M1w = (const float*)d_in[11];
    const float* M1b = (const float*)d_in[12];
    const float* M2w = (const float*)d_in[13];
    const float* M2b = (const float*)d_in[14];
    const float* M3w = (const float*)d_in[15];
    const float* M3b = (const float*)d_in[16];
    const float* M4w = (const float*)d_in[17];
    const float* M4b = (const float*)d_in[18];
    float* out = (float*)d_out;

    void *p_h1, *p_h2, *p_x11, *p_x12;
    cudaGetSymbolAddress(&p_h1, g_h1);
    cudaGetSymbolAddress(&p_h2, g_h2);
    cudaGetSymbolAddress(&p_x11, g_x11);
    cudaGetSymbolAddress(&p_x12, g_x12);
    float* h1 = (float*)p_h1;   float* h2 = (float*)p_h2;
    float* x11 = (float*)p_x11; float* x12 = (float*)p_x12;

    const int TPB = 256;
    int nodeBlocks = (N_NODES + TPB - 1) / TPB;
    int edgeBlocks = (2 * E_EDGES + TPB - 1) / TPB;
    int agg1Blocks = (2 * N_NODES * 32 + TPB - 1) / TPB;
    int agg2Blocks = (N_NODES * 32 + TPB - 1) / TPB;

    // CSR build (once, reused by both layers)
    k_init<<<nodeBlocks, TPB>>>();
    k_deg<<<edgeBlocks, TPB>>>(ei1, ew1, ei2, ew2);
    k_scan<<<2, 1024>>>();
    k_dis<<<nodeBlocks, TPB>>>();
    k_fill<<<edgeBlocks, TPB>>>(ei1, ew1, ei2, ew2);

    dim3 gg((N_NODES + 127) / 128, 2);
    // layer 1
    k_gemm<<<gg, TPB>>>(fm0, fm1, W1, h1, h2);
    k_agg1<<<agg1Blocks, TPB>>>(h1, h2, x11, x12, b1);
    // layer 2 (+ fused pooling)
    k_gemm<<<gg, TPB>>>(x11, x12, W2, h1, h2);
    k_agg2<<<agg2Blocks, TPB>>>(h1, h2, b2, batch);
    // MLP
    k_mlp<<<NGRAPH, 128>>>(M1w, M1b, M2w, M2b, M3w, M3b, M4w, M4b, out);
}

// round 3
// speedup vs baseline: 1.4944x; 1.0931x over previous
#include <cuda_runtime.h>

#define N_NODES 50000
#define E_EDGES 800000
#define D 128
#define NGRAPH 64

// ---------------- scratch (static __device__, no allocation) ----------------
__device__ float g_h1[N_NODES * D];
__device__ float g_h2[N_NODES * D];
__device__ float g_x11[N_NODES * D];
__device__ float g_x12[N_NODES * D];
__device__ float g_deg1[N_NODES];
__device__ float g_deg2[N_NODES];
__device__ float g_dis1[N_NODES];
__device__ float g_dis2[N_NODES];
__device__ int   g_c1[N_NODES];
__device__ int   g_c2[N_NODES];
__device__ int   g_rp1[N_NODES + 1];
__device__ int   g_rp2[N_NODES + 1];
__device__ int   g_cur1[N_NODES];
__device__ int   g_cur2[N_NODES];
__device__ int2  g_m1[E_EDGES];
__device__ int2  g_m2[E_EDGES];
__device__ float g_sums[NGRAPH * D];
__device__ float g_cnt[NGRAPH];

// ---------------- helpers ----------------
__device__ __forceinline__ void red_add_v4(float* p, float a, float b, float c, float d) {
    asm volatile(
        "{\n\t"
        ".reg .u64 q;\n\t"
        "cvta.to.global.u64 q, %0;\n\t"
        "red.global.add.v4.f32 [q], {%1, %2, %3, %4};\n\t"
        "}"
        :: "l"(p), "f"(a), "f"(b), "f"(c), "f"(d) : "memory");
}

__device__ __forceinline__ unsigned long long dup2(float x) {
    unsigned long long r;
    asm("mov.b64 %0, {%1, %1};" : "=l"(r) : "f"(x));
    return r;
}
__device__ __forceinline__ void fma2(unsigned long long& c, unsigned long long a,
                                     unsigned long long b) {
    asm("fma.rn.f32x2 %0, %1, %2, %0;" : "+l"(c) : "l"(a), "l"(b));
}

// ---------------- CSR build ----------------

__global__ void k_init() {
    int i = blockIdx.x * blockDim.x + threadIdx.x;
    if (i < N_NODES) {
        g_deg1[i] = 1.0f; g_deg2[i] = 1.0f;
        g_c1[i] = 0; g_c2[i] = 0;
    }
    if (i < NGRAPH * D) g_sums[i] = 0.0f;
    if (i < NGRAPH) g_cnt[i] = 0.0f;
}

__global__ void k_deg(const int* __restrict__ ei1, const float* __restrict__ ew1,
                      const int* __restrict__ ei2, const float* __restrict__ ew2) {
    int t = blockIdx.x * blockDim.x + threadIdx.x;
    if (t < E_EDGES) {
        int d = ei1[E_EDGES + t];
        atomicAdd(&g_deg1[d], ew1[t]);
        atomicAdd(&g_c1[d], 1);
    } else if (t < 2 * E_EDGES) {
        int e = t - E_EDGES;
        int d = ei2[E_EDGES + e];
        atomicAdd(&g_deg2[d], ew2[e]);
        atomicAdd(&g_c2[d], 1);
    }
}

__global__ __launch_bounds__(1024) void k_scan() {
    const int T = 1024;
    const int CH = (N_NODES + T - 1) / T;
    int g = blockIdx.x;
    const int* cnt = g ? g_c2 : g_c1;
    int* rp = g ? g_rp2 : g_rp1;
    int* cur = g ? g_cur2 : g_cur1;
    __shared__ int sh[T];
    int t = threadIdx.x;
    int base = t * CH;
    int s = 0;
    for (int i = 0; i < CH; i++) {
        int idx = base + i;
        s += (idx < N_NODES) ? cnt[idx] : 0;
    }
    sh[t] = s;
    __syncthreads();
    for (int off = 1; off < T; off <<= 1) {
        int v = (t >= off) ? sh[t - off] : 0;
        __syncthreads();
        sh[t] += v;
        __syncthreads();
    }
    int run = (t == 0) ? 0 : sh[t - 1];
    for (int i = 0; i < CH; i++) {
        int idx = base + i;
        if (idx < N_NODES) {
            rp[idx] = run;
            cur[idx] = run;
            run += cnt[idx];
        }
    }
    if (t == T - 1) rp[N_NODES] = run;
}

__global__ void k_dis() {
    int i = blockIdx.x * blockDim.x + threadIdx.x;
    if (i < N_NODES) {
        g_dis1[i] = rsqrtf(g_deg1[i]);
        g_dis2[i] = rsqrtf(g_deg2[i]);
    }
}

__global__ void k_fill(const int* __restrict__ ei1, const float* __restrict__ ew1,
                       const int* __restrict__ ei2, const float* __restrict__ ew2) {
    int t = blockIdx.x * blockDim.x + threadIdx.x;
    if (t < E_EDGES) {
        int s = ei1[t], d = ei1[E_EDGES + t];
        float norm = g_dis1[s] * ew1[t] * g_dis1[d];
        int pos = atomicAdd(&g_cur1[d], 1);
        g_m1[pos] = make_int2(s, __float_as_int(norm));
    } else if (t < 2 * E_EDGES) {
        int e = t - E_EDGES;
        int s = ei2[e], d = ei2[E_EDGES + e];
        float norm = g_dis2[s] * ew2[e] * g_dis2[d];
        int pos = atomicAdd(&g_cur2[d], 1);
        g_m2[pos] = make_int2(s, __float_as_int(norm));
    }
}

// ---------------- GEMM: C[N,128] = A[N,128] @ W[128,128], f32x2 ----------------
__global__ __launch_bounds__(256) void k_gemm1m(
    const float* __restrict__ A, const float* __restrict__ W, float* __restrict__ C) {
    __shared__ __align__(16) float As[16][132];
    __shared__ __align__(16) float Ws[16][128];

    int row0 = blockIdx.x * 128;
    int t = threadIdx.x;
    int tx = t & 15;
    int ty = t >> 4;

    unsigned long long acc2[4][8];
#pragma unroll
    for (int i = 0; i < 4; i++)
#pragma unroll
        for (int j = 0; j < 8; j++) acc2[i][j] = 0ull;

    for (int kk = 0; kk < 128; kk += 16) {
#pragma unroll
        for (int i = 0; i < 2; i++) {
            int f4 = t * 2 + i;
            int r = f4 >> 2;
            int q = f4 & 3;
            int grow = row0 + r;
            float4 v = make_float4(0.f, 0.f, 0.f, 0.f);
            if (grow < N_NODES)
                v = *(const float4*)(A + grow * 128 + kk + q * 4);
            As[q * 4 + 0][r] = v.x;
            As[q * 4 + 1][r] = v.y;
            As[q * 4 + 2][r] = v.z;
            As[q * 4 + 3][r] = v.w;
        }
#pragma unroll
        for (int i = 0; i < 2; i++) {
            int f4 = t * 2 + i;
            int r = f4 >> 5;
            int c = (f4 & 31) * 4;
            *(float4*)&Ws[r][c] = *(const float4*)(W + (kk + r) * 128 + c);
        }
        __syncthreads();

#pragma unroll
        for (int k = 0; k < 16; k++) {
            ulonglong2 av0 = *(const ulonglong2*)&As[k][ty * 8];
            ulonglong2 av1 = *(const ulonglong2*)&As[k][ty * 8 + 4];
            unsigned long long ap[4] = {av0.x, av0.y, av1.x, av1.y};
            float4 b0 = *(const float4*)&Ws[k][tx * 8];
            float4 b1 = *(const float4*)&Ws[k][tx * 8 + 4];
            unsigned long long bd[8];
            bd[0] = dup2(b0.x); bd[1] = dup2(b0.y); bd[2] = dup2(b0.z); bd[3] = dup2(b0.w);
            bd[4] = dup2(b1.x); bd[5] = dup2(b1.y); bd[6] = dup2(b1.z); bd[7] = dup2(b1.w);
#pragma unroll
            for (int i = 0; i < 4; i++)
#pragma unroll
                for (int j = 0; j < 8; j++) fma2(acc2[i][j], ap[i], bd[j]);
        }
        __syncthreads();
    }

#pragma unroll
    for (int i2 = 0; i2 < 4; i2++) {
        float2 f[8];
#pragma unroll
        for (int j = 0; j < 8; j++) f[j] = *(float2*)&acc2[i2][j];
#pragma unroll
        for (int rs = 0; rs < 2; rs++) {
            int r = row0 + ty * 8 + i2 * 2 + rs;
            if (r < N_NODES) {
                float4 v0, v1;
                v0.x = rs ? f[0].y : f[0].x; v0.y = rs ? f[1].y : f[1].x;
                v0.z = rs ? f[2].y : f[2].x; v0.w = rs ? f[3].y : f[3].x;
                v1.x = rs ? f[4].y : f[4].x; v1.y = rs ? f[5].y : f[5].x;
                v1.z = rs ? f[6].y : f[6].x; v1.w = rs ? f[7].y : f[7].x;
                *(float4*)(C + r * 128 + tx * 8) = v0;
                *(float4*)(C + r * 128 + tx * 8 + 4) = v1;
            }
        }
    }
}

// ---------------- aggregation: one graph, warp per node ----------------
__global__ __launch_bounds__(256) void k_agg1g(
    const float* __restrict__ H, float* __restrict__ X,
    const float* __restrict__ bias,
    const int* __restrict__ rp, const int2* __restrict__ meta,
    const float* __restrict__ dis) {
    int d = (blockIdx.x * blockDim.x + threadIdx.x) >> 5;
    int lane = threadIdx.x & 31;
    if (d >= N_NODES) return;

    int beg = rp[d], end = rp[d + 1];
    float n2 = dis[d]; n2 *= n2;
    float4 bv = *(const float4*)(bias + lane * 4);
    float4 hd = *(const float4*)(H + d * 128 + lane * 4);
    float4 acc = make_float4(fmaf(n2, hd.x, bv.x), fmaf(n2, hd.y, bv.y),
                             fmaf(n2, hd.z, bv.z), fmaf(n2, hd.w, bv.w));

    for (int base = beg; base < end; base += 32) {
        int2 mm = make_int2(0, 0);
        if (base + lane < end) mm = __ldg(&meta[base + lane]);
        int m = min(32, end - base);
        int j = 0;
        for (; j + 4 <= m; j += 4) {
            int s0 = __shfl_sync(0xffffffffu, mm.x, j);
            int s1 = __shfl_sync(0xffffffffu, mm.x, j + 1);
            int s2 = __shfl_sync(0xffffffffu, mm.x, j + 2);
            int s3 = __shfl_sync(0xffffffffu, mm.x, j + 3);
            float w0 = __int_as_float(__shfl_sync(0xffffffffu, mm.y, j));
            float w1 = __int_as_float(__shfl_sync(0xffffffffu, mm.y, j + 1));
            float w2 = __int_as_float(__shfl_sync(0xffffffffu, mm.y, j + 2));
            float w3 = __int_as_float(__shfl_sync(0xffffffffu, mm.y, j + 3));
            float4 v0 = __ldg((const float4*)(H + s0 * 128 + lane * 4));
            float4 v1 = __ldg((const float4*)(H + s1 * 128 + lane * 4));
            float4 v2 = __ldg((const float4*)(H + s2 * 128 + lane * 4));
            float4 v3 = __ldg((const float4*)(H + s3 * 128 + lane * 4));
            acc.x = fmaf(w0, v0.x, fmaf(w1, v1.x, fmaf(w2, v2.x, fmaf(w3, v3.x, acc.x))));
            acc.y = fmaf(w0, v0.y, fmaf(w1, v1.y, fmaf(w2, v2.y, fmaf(w3, v3.y, acc.y))));
            acc.z = fmaf(w0, v0.z, fmaf(w1, v1.z, fmaf(w2, v2.z, fmaf(w3, v3.z, acc.z))));
            acc.w = fmaf(w0, v0.w, fmaf(w1, v1.w, fmaf(w2, v2.w, fmaf(w3, v3.w, acc.w))));
        }
        for (; j < m; j++) {
            int s = __shfl_sync(0xffffffffu, mm.x, j);
            float w = __int_as_float(__shfl_sync(0xffffffffu, mm.y, j));
            float4 v = __ldg((const float4*)(H + s * 128 + lane * 4));
            acc.x = fmaf(w, v.x, acc.x); acc.y = fmaf(w, v.y, acc.y);
            acc.z = fmaf(w, v.z, acc.z); acc.w = fmaf(w, v.w, acc.w);
        }
    }
    *(float4*)(X + d * 128 + lane * 4) = acc;
}

// ---------------- layer-2 aggregation fused with pooling ----------------
__global__ __launch_bounds__(256) void k_agg2(
    const float* __restrict__ H1, const float* __restrict__ H2,
    const float* __restrict__ bias, const int* __restrict__ batch) {
    int wid = (blockIdx.x * blockDim.x + threadIdx.x) >> 5;
    int lane = threadIdx.x & 31;
    if (wid >= N_NODES) return;
    int d = wid;
    float4 bv = *(const float4*)(bias + lane * 4);
    float4 acc1, acc2v;

#pragma unroll
    for (int g = 0; g < 2; g++) {
        const int2* meta = g ? g_m2 : g_m1;
        const int* rp = g ? g_rp2 : g_rp1;
        const float* H = g ? H2 : H1;
        const float* dis = g ? g_dis2 : g_dis1;
        int beg = rp[d], end = rp[d + 1];
        float n2 = dis[d]; n2 *= n2;
        float4 hd = *(const float4*)(H + d * 128 + lane * 4);
        float4 acc = make_float4(fmaf(n2, hd.x, bv.x), fmaf(n2, hd.y, bv.y),
                                 fmaf(n2, hd.z, bv.z), fmaf(n2, hd.w, bv.w));
        for (int base = beg; base < end; base += 32) {
            int2 mm = make_int2(0, 0);
            if (base + lane < end) mm = __ldg(&meta[base + lane]);
            int m = min(32, end - base);
            int j = 0;
            for (; j + 4 <= m; j += 4) {
                int s0 = __shfl_sync(0xffffffffu, mm.x, j);
                int s1 = __shfl_sync(0xffffffffu, mm.x, j + 1);
                int s2 = __shfl_sync(0xffffffffu, mm.x, j + 2);
                int s3 = __shfl_sync(0xffffffffu, mm.x, j + 3);
                float w0 = __int_as_float(__shfl_sync(0xffffffffu, mm.y, j));
                float w1 = __int_as_float(__shfl_sync(0xffffffffu, mm.y, j + 1));
                float w2 = __int_as_float(__shfl_sync(0xffffffffu, mm.y, j + 2));
                float w3 = __int_as_float(__shfl_sync(0xffffffffu, mm.y, j + 3));
                float4 v0 = __ldg((const float4*)(H + s0 * 128 + lane * 4));
                float4 v1 = __ldg((const float4*)(H + s1 * 128 + lane * 4));
                float4 v2 = __ldg((const float4*)(H + s2 * 128 + lane * 4));
                float4 v3 = __ldg((const float4*)(H + s3 * 128 + lane * 4));
                acc.x = fmaf(w0, v0.x, fmaf(w1, v1.x, fmaf(w2, v2.x, fmaf(w3, v3.x, acc.x))));
                acc.y = fmaf(w0, v0.y, fmaf(w1, v1.y, fmaf(w2, v2.y, fmaf(w3, v3.y, acc.y))));
                acc.z = fmaf(w0, v0.z, fmaf(w1, v1.z, fmaf(w2, v2.z, fmaf(w3, v3.z, acc.z))));
                acc.w = fmaf(w0, v0.w, fmaf(w1, v1.w, fmaf(w2, v2.w, fmaf(w3, v3.w, acc.w))));
            }
            for (; j < m; j++) {
                int s = __shfl_sync(0xffffffffu, mm.x, j);
                float w = __int_as_float(__shfl_sync(0xffffffffu, mm.y, j));
                float4 v = __ldg((const float4*)(H + s * 128 + lane * 4));
                acc.x = fmaf(w, v.x, acc.x); acc.y = fmaf(w, v.y, acc.y);
                acc.z = fmaf(w, v.z, acc.z); acc.w = fmaf(w, v.w, acc.w);
            }
        }
        if (g == 0) acc1 = acc; else acc2v = acc;
    }

    int off = d * 128 + lane * 4;
    float4 a11 = *(const float4*)(g_x11 + off);
    float4 a12 = *(const float4*)(g_x12 + off);
    float px = (a12.x - a11.x) * (acc2v.x - acc1.x);
    float py = (a12.y - a11.y) * (acc2v.y - acc1.y);
    float pz = (a12.z - a11.z) * (acc2v.z - acc1.z);
    float pw = (a12.w - a11.w) * (acc2v.w - acc1.w);
    int gph = batch[d];
    red_add_v4(g_sums + gph * 128 + lane * 4, px, py, pz, pw);
    if (lane == 0) atomicAdd(&g_cnt[gph], 1.0f);
}

// ---------------- final MLP ----------------
__global__ __launch_bounds__(128) void k_mlp(
    const float* __restrict__ M1w, const float* __restrict__ M1b,
    const float* __restrict__ M2w, const float* __restrict__ M2b,
    const float* __restrict__ M3w, const float* __restrict__ M3b,
    const float* __restrict__ M4w, const float* __restrict__ M4b,
    float* __restrict__ out) {
    __shared__ float gv[128], h1s[128], h2s[64], h3s[32];
    int g = blockIdx.x;
    int t = threadIdx.x;
    float cnt = fmaxf(g_cnt[g], 1.0f);
    gv[t] = g_sums[g * 128 + t] / cnt;
    __syncthreads();
    float acc = M1b[t];
#pragma unroll 8
    for (int c = 0; c < 128; c++) acc += gv[c] * M1w[c * 128 + t];
    h1s[t] = acc;
    __syncthreads();
    if (t < 64) {
        acc = M2b[t];
#pragma unroll 8
        for (int c = 0; c < 128; c++) acc += h1s[c] * M2w[c * 64 + t];
        h2s[t] = acc;
    }
    __syncthreads();
    if (t < 32) {
        acc = M3b[t];
#pragma unroll 8
        for (int c = 0; c < 64; c++) acc += h2s[c] * M3w[c * 32 + t];
        h3s[t] = acc;
    }
    __syncthreads();
    if (t < 32) {
        float v = h3s[t] * M4w[t];
#pragma unroll
        for (int off = 16; off > 0; off >>= 1)
            v += __shfl_down_sync(0xffffffff, v, off);
        if (t == 0) out[g] = v + M4b[0];
    }
}

// ---------------- launch ----------------
extern "C" void kernel_launch(void* const* d_in, const int* in_sizes, int n_in,
                              void* d_out, int out_size) {
    const int*   ei1  = (const int*)d_in[0];
    const float* ew1  = (const float*)d_in[1];
    const int*   ei2  = (const int*)d_in[2];
    const float* ew2  = (const float*)d_in[3];
    const float* fm0  = (const float*)d_in[4];
    const float* fm1  = (const float*)d_in[5];
    const int*   batch = (const int*)d_in[6];
    const float* W1  = (const float*)d_in[7];
    const float* b1  = (const float*)d_in[8];
    const float* W2  = (const float*)d_in[9];
    const float* b2  = (const float*)d_in[10];
    const float* M1w = (const float*)d_in[11];
    const float* M1b = (const float*)d_in[12];
    const float* M2w = (const float*)d_in[13];
    const float* M2b = (const float*)d_in[14];
    const float* M3w = (const float*)d_in[15];
    const float* M3b = (const float*)d_in[16];
    const float* M4w = (const float*)d_in[17];
    const float* M4b = (const float*)d_in[18];
    float* out = (float*)d_out;

    void *p_h1, *p_h2, *p_x11, *p_x12;
    void *p_rp1, *p_rp2, *p_m1, *p_m2, *p_dis1, *p_dis2;
    cudaGetSymbolAddress(&p_h1, g_h1);
    cudaGetSymbolAddress(&p_h2, g_h2);
    cudaGetSymbolAddress(&p_x11, g_x11);
    cudaGetSymbolAddress(&p_x12, g_x12);
    cudaGetSymbolAddress(&p_rp1, g_rp1);
    cudaGetSymbolAddress(&p_rp2, g_rp2);
    cudaGetSymbolAddress(&p_m1, g_m1);
    cudaGetSymbolAddress(&p_m2, g_m2);
    cudaGetSymbolAddress(&p_dis1, g_dis1);
    cudaGetSymbolAddress(&p_dis2, g_dis2);
    float* h1 = (float*)p_h1;   float* h2 = (float*)p_h2;
    float* x11 = (float*)p_x11; float* x12 = (float*)p_x12;

    // Lazy one-time stream/event creation. First call is the uncaptured
    // correctness run, so creation never happens during graph capture.
    static cudaStream_t sA = nullptr, sB = nullptr;
    static cudaEvent_t eF = nullptr, eCSR = nullptr, eA = nullptr, eB = nullptr;
    if (sA == nullptr) {
        cudaStreamCreateWithFlags(&sA, cudaStreamNonBlocking);
        cudaStreamCreateWithFlags(&sB, cudaStreamNonBlocking);
        cudaEventCreateWithFlags(&eF, cudaEventDisableTiming);
        cudaEventCreateWithFlags(&eCSR, cudaEventDisableTiming);
        cudaEventCreateWithFlags(&eA, cudaEventDisableTiming);
        cudaEventCreateWithFlags(&eB, cudaEventDisableTiming);
    }

    const int TPB = 256;
    int nodeBlocks = (N_NODES + TPB - 1) / TPB;
    int edgeBlocks = (2 * E_EDGES + TPB - 1) / TPB;
    int gemmBlocks = (N_NODES + 127) / 128;
    int aggBlocks  = (N_NODES * 32 + TPB - 1) / TPB;

    // fork: per-graph gemm1 chains run concurrently with CSR build
    cudaEventRecord(eF, 0);
    cudaStreamWaitEvent(sA, eF, 0);
    cudaStreamWaitEvent(sB, eF, 0);
    k_gemm1m<<<gemmBlocks, TPB, 0, sA>>>(fm0, W1, h1);
    k_gemm1m<<<gemmBlocks, TPB, 0, sB>>>(fm1, W1, h2);

    // CSR build chain on default stream
    k_init<<<nodeBlocks, TPB>>>();
    k_deg<<<edgeBlocks, TPB>>>(ei1, ew1, ei2, ew2);
    k_scan<<<2, 1024>>>();
    k_dis<<<nodeBlocks, TPB>>>();
    k_fill<<<edgeBlocks, TPB>>>(ei1, ew1, ei2, ew2);
    cudaEventRecord(eCSR, 0);
    cudaStreamWaitEvent(sA, eCSR, 0);
    cudaStreamWaitEvent(sB, eCSR, 0);

    // per-graph: agg1 then gemm2 (h buffers reused after agg1 reads them)
    k_agg1g<<<aggBlocks, TPB, 0, sA>>>(h1, x11, b1, (const int*)p_rp1,
                                       (const int2*)p_m1, (const float*)p_dis1);
    k_gemm1m<<<gemmBlocks, TPB, 0, sA>>>(x11, W2, h1);
    k_agg1g<<<aggBlocks, TPB, 0, sB>>>(h2, x12, b1, (const int*)p_rp2,
                                       (const int2*)p_m2, (const float*)p_dis2);
    k_gemm1m<<<gemmBlocks, TPB, 0, sB>>>(x12, W2, h2);

    cudaEventRecord(eA, sA);
    cudaEventRecord(eB, sB);
    cudaStreamWaitEvent(0, eA, 0);
    cudaStreamWaitEvent(0, eB, 0);

    // join: layer-2 aggregation fused with pooling, then MLP
    k_agg2<<<aggBlocks, TPB>>>(h1, h2, b2, batch);
    k_mlp<<<NGRAPH, 128>>>(M1w, M1b, M2w, M2b, M3w, M3b, M4w, M4b, out);
}